// round 16
// baseline (speedup 1.0000x reference)
#include <cuda_runtime.h>
#include <cuda_bf16.h>
#include <cstdint>

#define N_PIX 4096
#define M_PIX 1024

// cp.async helpers (16B per op)
#define CPA(dst32, srcp) \
    asm volatile("cp.async.ca.shared.global [%0], [%1], 16;" :: "r"(dst32), "l"(srcp) : "memory")
#define CP_COMMIT() asm volatile("cp.async.commit_group;" ::: "memory")
#define CP_WAIT0()  asm volatile("cp.async.wait_group 0;" ::: "memory")

// ldmatrix x4 (b16)
#define LDMX4(r0, r1, r2, r3, addr) \
    asm volatile("ldmatrix.sync.aligned.m8n8.x4.shared.b16 {%0,%1,%2,%3}, [%4];" \
        : "=r"(r0), "=r"(r1), "=r"(r2), "=r"(r3) : "r"(addr))
#define LDMX4T(r0, r1, r2, r3, addr) \
    asm volatile("ldmatrix.sync.aligned.m8n8.x4.trans.shared.b16 {%0,%1,%2,%3}, [%4];" \
        : "=r"(r0), "=r"(r1), "=r"(r2), "=r"(r3) : "r"(addr))

// m16n8k16 bf16 MMA, fp32 accumulate
#define MMA_BF16(d, a0, a1, a2, a3, b0, b1) \
    asm volatile("mma.sync.aligned.m16n8k16.row.col.f32.bf16.bf16.f32 " \
        "{%0,%1,%2,%3}, {%4,%5,%6,%7}, {%8,%9}, {%0,%1,%2,%3};" \
        : "+f"(d[0]), "+f"(d[1]), "+f"(d[2]), "+f"(d[3]) \
        : "r"(a0), "r"(a1), "r"(a2), "r"(a3), "r"(b0), "r"(b1))

__device__ __forceinline__ uint32_t pkbf(float a, float b) {
    __nv_bfloat162 h = __float22bfloat162_rn(make_float2(a, b));
    return *reinterpret_cast<uint32_t*>(&h);
}
__device__ __forceinline__ float ex2f(float x) {
    float r;
    asm("ex2.approx.f32 %0, %1;" : "=f"(r) : "f"(x));
    return r;
}

// Scratch (device globals — no allocation allowed)
__device__ __align__(16) __nv_bfloat16 g_q[16 * 16 * N_PIX];   // [b][16][n] bf16, pre-scaled log2(e)
__device__ __align__(16) __nv_bfloat16 g_k[16 * M_PIX * 16];   // [b][m][16] bf16
__device__ __align__(16) __nv_bfloat16 g_v[16 * 64 * M_PIX];   // [b][64][m] bf16

// ---------------------------------------------------------------------------
// Kernel 1 (high-occupancy bf16 GEMM): out[96][128px] = W*x, 2x2 maxpool.
// All 128 channels of x staged ONCE as bf16 [c][px] (34KB); 6 output m-tiles
// looped serially with only 8 accumulator regs -> ~50 regs -> 3 CTAs/SM.
// Pooling per m-tile through a small reused scratch.
// ---------------------------------------------------------------------------
#define K1_W    0        // bf16 [96][136]  = 6528 fl
#define K1_X    6528     // bf16 [128][136] = 8704 fl
#define K1_PB   15232    // fp32 [16][2][34] = 1088 fl
#define K1_SMEM 16320    // floats = 65280 B

__global__ __launch_bounds__(256, 3) void proj_pool_kernel(
    const float* __restrict__ x,
    const float* __restrict__ wq,
    const float* __restrict__ wk,
    const float* __restrict__ wv)
{
    extern __shared__ float sm[];
    __nv_bfloat16* sWb = (__nv_bfloat16*)(sm + K1_W);     // [96][136]
    __nv_bfloat16* sX  = (__nv_bfloat16*)(sm + K1_X);     // [128][136]
    float*         pb  = sm + K1_PB;                      // [16][2][34]

    const int t    = threadIdx.x;
    const int lane = t & 31;
    const int w    = t >> 5;
    const int g    = lane >> 2;
    const int tig  = lane & 3;
    const int b    = blockIdx.y;
    const int px0  = blockIdx.x * 128;

    const float* xb = x + (size_t)b * 128 * N_PIX;
    const uint32_t sbase = (uint32_t)__cvta_generic_to_shared(sm);

    // ---- stage x: 16 float4 per thread, LDG -> CVT -> STS bf16 ----
    const int xr_row = t >> 3;             // channel within 32-group
    const int xr_col = (t & 7) * 4;        // float col base (+q*32)
#pragma unroll
    for (int half = 0; half < 2; half++) {
        float4 xr[8];
#pragma unroll
        for (int i = 0; i < 8; i++) {
            int q = i & 3, grp = half * 2 + (i >> 2);
            xr[i] = *(const float4*)&xb[(size_t)(grp * 32 + xr_row) * N_PIX
                                        + px0 + xr_col + q * 32];
        }
#pragma unroll
        for (int i = 0; i < 8; i++) {
            int q = i & 3, grp = half * 2 + (i >> 2);
            uint2 u;
            u.x = pkbf(xr[i].x, xr[i].y);
            u.y = pkbf(xr[i].z, xr[i].w);
            *(uint2*)(sX + (grp * 32 + xr_row) * 136 + xr_col + q * 32) = u;
        }
    }

    // ---- stage W bf16 [o][c] stride 136 ----
    for (int i = t; i < 6144; i += 256) {
        int o = i >> 6, c2 = i & 63;
        const float* src = (o < 16) ? (wq + o * 128)
                         : (o < 32) ? (wk + (o - 16) * 128)
                                    : (wv + (o - 32) * 128);
        *(uint32_t*)(sWb + o * 136 + 2 * c2) = pkbf(src[2 * c2], src[2 * c2 + 1]);
    }
    __syncthreads();

    const int nA   = w * 16;
    const int matI = lane >> 3, ii = lane & 7;
    const uint32_t aB = sbase
        + (uint32_t)(ii + 8 * (matI & 1)) * 272u + (uint32_t)(matI >> 1) * 16u;
    const uint32_t bB = sbase + (uint32_t)K1_X * 4u
        + (uint32_t)(ii + 8 * (matI & 1)) * 272u + (uint32_t)(nA + 8 * (matI >> 1)) * 2u;

    const int mbase = blockIdx.x * 32;
    const float L2E = 1.44269504f;

#pragma unroll 1
    for (int mt = 0; mt < 6; mt++) {
        float dd[8];
#pragma unroll
        for (int j = 0; j < 8; j++) dd[j] = 0.f;

#pragma unroll
        for (int ks = 0; ks < 8; ks++) {
            uint32_t x0, x1, x2, x3, a0, a1, a2, a3;
            LDMX4T(x0, x1, x2, x3, bB + (uint32_t)ks * 16u * 272u);
            LDMX4(a0, a1, a2, a3, aB + (uint32_t)(mt * 16) * 272u + (uint32_t)ks * 32u);
            MMA_BF16((&dd[0]), a0, a1, a2, a3, x0, x1);
            MMA_BF16((&dd[4]), a0, a1, a2, a3, x2, x3);
        }

        if (mt == 0) {
            // q: bf16, pre-scaled by log2(e)
#pragma unroll
            for (int nb = 0; nb < 2; nb++) {
                int n = nA + nb * 8 + 2 * tig;
                size_t qi0 = ((size_t)(b * 16 + g))     * N_PIX + px0 + n;
                size_t qi1 = ((size_t)(b * 16 + g + 8)) * N_PIX + px0 + n;
                *(uint32_t*)&g_q[qi0] = pkbf(dd[nb * 4]     * L2E, dd[nb * 4 + 1] * L2E);
                *(uint32_t*)&g_q[qi1] = pkbf(dd[nb * 4 + 2] * L2E, dd[nb * 4 + 3] * L2E);
            }
        } else {
            // k/v: horizontal max intra-thread -> scratch, vertical max -> gmem
#pragma unroll
            for (int nb = 0; nb < 2; nb++) {
                int n = nA + nb * 8 + 2 * tig;
                int rrow = n >> 6;
                int wp = (n & 63) >> 1;
                pb[g * 68 + rrow * 34 + wp]       = fmaxf(dd[nb * 4],     dd[nb * 4 + 1]);
                pb[(g + 8) * 68 + rrow * 34 + wp] = fmaxf(dd[nb * 4 + 2], dd[nb * 4 + 3]);
            }
            __syncthreads();
#pragma unroll
            for (int i2 = 0; i2 < 2; i2++) {
                int i = t + i2 * 256;          // 0..511
                int ch = i >> 5, wp = i & 31;
                float r = fmaxf(pb[ch * 68 + wp], pb[ch * 68 + 34 + wp]);
                if (mt == 1)
                    g_k[((size_t)(b * M_PIX + mbase + wp)) * 16 + ch] = __float2bfloat16_rn(r);
                else
                    g_v[((b * 64 + (mt - 2) * 16 + ch) << 10) + mbase + wp] = __float2bfloat16_rn(r);
            }
            if (mt < 5) __syncthreads();       // protect pb reuse
        }
    }
}

// ---------------------------------------------------------------------------
// Kernel 2: FA2-style fused attention (byte-identical to R15, 55.7us).
// ---------------------------------------------------------------------------
#define SV_OFF(buf)  ((buf) ? 4352u : 0u)
#define SK_OFF(buf)  (8704u + ((buf) ? 1536u : 0u))
#define SO_OFF       0u      // bf16 [128][72] = 4608 fl
#define SWO_OFF      4608u   // bf16 [128][72] = 4608 fl
#define SSUM_OFF     17408u
#define SINV_OFF     17536u
#define SMEM2_FLOATS 17664

__device__ __forceinline__ void stage_chunk(
    uint32_t sbase, int buf, int chk, int t,
    const __nv_bfloat16* __restrict__ gkb, const __nv_bfloat16* __restrict__ gvb)
{
    uint32_t kdst = sbase + SK_OFF(buf) * 4u;
    uint32_t vdst = sbase + SV_OFF(buf) * 4u;
    {
        int m = t >> 1, h = t & 1;
        CPA(kdst + (uint32_t)m * 48u + (uint32_t)h * 16u,
            gkb + ((size_t)(chk * 128 + m)) * 16 + h * 8);
    }
#pragma unroll
    for (int q = 0; q < 4; q++) {
        int i = t + q * 256;
        int r = i >> 4, u = i & 15;
        CPA(vdst + (uint32_t)r * 272u + (uint32_t)u * 16u,
            gvb + ((size_t)r << 10) + chk * 128 + u * 8);
    }
}

__global__ __launch_bounds__(256, 2) void attn_kernel(
    const float* __restrict__ x,
    const float* __restrict__ wo,
    const float* __restrict__ gamma,
    float* __restrict__ out)
{
    extern __shared__ float sm[];
    float* sSum = sm + SSUM_OFF;
    float* sInv = sm + SINV_OFF;

    const int t    = threadIdx.x;
    const int w    = t >> 5;
    const int lane = t & 31;
    const int b    = blockIdx.y;
    const int n0   = blockIdx.x * 128;

    const int g    = lane >> 2;
    const int tig  = lane & 3;
    const int nw   = w * 16;
    const int matI = lane >> 3, ii = lane & 7;

    const uint32_t sbase = (uint32_t)__cvta_generic_to_shared(sm);
    const __nv_bfloat16* gkb = g_k + (size_t)b * M_PIX * 16;
    const __nv_bfloat16* gvb = g_v + (size_t)b * 64 * M_PIX;

    const uint32_t kOff = (uint32_t)(ii + 8 * (matI >> 1)) * 48u + (uint32_t)(matI & 1) * 16u;
    const uint32_t vOff = (uint32_t)(ii + 8 * (matI >> 1)) * 272u + (uint32_t)(matI & 1) * 16u;

    stage_chunk(sbase, 0, 0, t, gkb, gvb);
    CP_COMMIT();

    uint32_t qa0, qa1, qa2, qa3;
    {
        const __nv_bfloat16* gq = g_q + (size_t)b * 16 * N_PIX + n0;
        const int nq = nw + g;
#define QLD(d, n) ((uint32_t)*(const unsigned short*)&gq[(size_t)(d) * N_PIX + (n)])
        qa0 = QLD(2 * tig, nq)         | (QLD(2 * tig + 1, nq)     << 16);
        qa1 = QLD(2 * tig, nq + 8)     | (QLD(2 * tig + 1, nq + 8) << 16);
        qa2 = QLD(2 * tig + 8, nq)     | (QLD(2 * tig + 9, nq)     << 16);
        qa3 = QLD(2 * tig + 8, nq + 8) | (QLD(2 * tig + 9, nq + 8) << 16);
#undef QLD
    }

    float oc[8][4];
#pragma unroll
    for (int i = 0; i < 8; i++)
#pragma unroll
        for (int j = 0; j < 4; j++) oc[i][j] = 0.f;
    float rsd[4] = {0.f, 0.f, 0.f, 0.f};
    const uint32_t ONE2 = 0x3F803F80u;

#pragma unroll 1
    for (int chk = 0; chk < 8; chk++) {
        const int buf = chk & 1;

        CP_WAIT0();
        __syncthreads();

        if (chk < 7) {
            stage_chunk(sbase, buf ^ 1, chk + 1, t, gkb, gvb);
            CP_COMMIT();
        }

        const uint32_t kBase = sbase + SK_OFF(buf) * 4u + kOff;
        const uint32_t vBase = sbase + SV_OFF(buf) * 4u + vOff;

#pragma unroll
        for (int h = 0; h < 2; h++) {
            float sd[8][4];
#pragma unroll
            for (int j = 0; j < 8; j++)
#pragma unroll
                for (int k = 0; k < 4; k++) sd[j][k] = 0.f;

#pragma unroll
            for (int u = 0; u < 4; u++) {
                uint32_t k0, k1, k2, k3;
                LDMX4(k0, k1, k2, k3, kBase + (uint32_t)(4 * h + u) * 768u);
                MMA_BF16(sd[2 * u],     qa0, qa1, qa2, qa3, k0, k1);
                MMA_BF16(sd[2 * u + 1], qa0, qa1, qa2, qa3, k2, k3);
            }

            uint32_t pa[4][4];
#pragma unroll
            for (int j = 0; j < 4; j++) {
                pa[j][0] = pkbf(ex2f(sd[2 * j][0]),     ex2f(sd[2 * j][1]));
                pa[j][1] = pkbf(ex2f(sd[2 * j][2]),     ex2f(sd[2 * j][3]));
                pa[j][2] = pkbf(ex2f(sd[2 * j + 1][0]), ex2f(sd[2 * j + 1][1]));
                pa[j][3] = pkbf(ex2f(sd[2 * j + 1][2]), ex2f(sd[2 * j + 1][3]));
                MMA_BF16(rsd, pa[j][0], pa[j][1], pa[j][2], pa[j][3], ONE2, ONE2);
            }

#pragma unroll
            for (int kt = 0; kt < 4; kt++) {
                const uint32_t colb = (uint32_t)(4 * h + kt) * 32u;
#pragma unroll
                for (int cp = 0; cp < 4; cp++) {
                    uint32_t v0, v1, v2, v3;
                    LDMX4(v0, v1, v2, v3, vBase + (uint32_t)cp * 4352u + colb);
                    MMA_BF16(oc[2 * cp],     pa[kt][0], pa[kt][1], pa[kt][2], pa[kt][3], v0, v1);
                    MMA_BF16(oc[2 * cp + 1], pa[kt][0], pa[kt][1], pa[kt][2], pa[kt][3], v2, v3);
                }
            }
        }
    }
    __syncthreads();

    __nv_bfloat16* sO = (__nv_bfloat16*)(sm + SO_OFF);
#pragma unroll
    for (int ct = 0; ct < 8; ct++) {
        int c = 8 * ct + 2 * tig;
        *(uint32_t*)&sO[(nw + g) * 72 + c]     = pkbf(oc[ct][0], oc[ct][1]);
        *(uint32_t*)&sO[(nw + g + 8) * 72 + c] = pkbf(oc[ct][2], oc[ct][3]);
    }
    if (tig == 0) {
        sSum[nw + g]     = rsd[0];
        sSum[nw + g + 8] = rsd[2];
    }
    __nv_bfloat16* sWo = (__nv_bfloat16*)(sm + SWO_OFF);
    for (int i = t; i < 4096; i += 256) {
        int o = i >> 5, c2 = i & 31;
        *(uint32_t*)&sWo[o * 72 + 2 * c2] = pkbf(wo[o * 64 + 2 * c2], wo[o * 64 + 2 * c2 + 1]);
    }
    __syncthreads();

    if (t < 128) sInv[t] = 1.f / sSum[t];
    __syncthreads();

    {
        const int o0 = w * 16;
        const uint32_t aE = sbase + SWO_OFF * 4u
            + (uint32_t)(o0 + ii + 8 * (matI & 1)) * 144u + (uint32_t)(matI >> 1) * 16u;
        const uint32_t bE = sbase + SO_OFF * 4u
            + (uint32_t)(ii + 8 * (matI >> 1)) * 144u + (uint32_t)(matI & 1) * 16u;

        float od[16][4];
#pragma unroll
        for (int j = 0; j < 16; j++)
#pragma unroll
            for (int k = 0; k < 4; k++) od[j][k] = 0.f;

#pragma unroll
        for (int ks = 0; ks < 4; ks++) {
            uint32_t a0, a1, a2, a3;
            LDMX4(a0, a1, a2, a3, aE + (uint32_t)ks * 32u);
#pragma unroll
            for (int nt2 = 0; nt2 < 8; nt2++) {
                uint32_t b0, b1, b2, b3;
                LDMX4(b0, b1, b2, b3, bE + (uint32_t)nt2 * 16u * 144u + (uint32_t)ks * 32u);
                MMA_BF16(od[2 * nt2],     a0, a1, a2, a3, b0, b1);
                MMA_BF16(od[2 * nt2 + 1], a0, a1, a2, a3, b2, b3);
            }
        }

        const float gm = gamma[0];
#pragma unroll
        for (int nt = 0; nt < 16; nt++) {
            int nn = 8 * nt + 2 * tig;
            float s0 = gm * sInv[nn];
            float s1 = gm * sInv[nn + 1];
            size_t gi0 = ((size_t)(b * 128 + o0 + g)) * N_PIX + n0 + nn;
            size_t gi1 = ((size_t)(b * 128 + o0 + g + 8)) * N_PIX + n0 + nn;
            float2 x0 = *(const float2*)&x[gi0];
            float2 x1 = *(const float2*)&x[gi1];
            float2 r0, r1;
            r0.x = fmaf(s0, od[nt][0], x0.x);
            r0.y = fmaf(s1, od[nt][1], x0.y);
            r1.x = fmaf(s0, od[nt][2], x1.x);
            r1.y = fmaf(s1, od[nt][3], x1.y);
            *(float2*)&out[gi0] = r0;
            *(float2*)&out[gi1] = r1;
        }
    }
}

// ---------------------------------------------------------------------------
extern "C" void kernel_launch(void* const* d_in, const int* in_sizes, int n_in,
                              void* d_out, int out_size)
{
    const float* x     = (const float*)d_in[0];
    const float* wq    = (const float*)d_in[1];
    const float* wk    = (const float*)d_in[2];
    const float* wv    = (const float*)d_in[3];
    const float* wo    = (const float*)d_in[4];
    const float* gamma = (const float*)d_in[5];
    float* out = (float*)d_out;

    const int smem1 = K1_SMEM * 4;        // 65280
    const int smem2 = SMEM2_FLOATS * 4;   // 70656

    cudaFuncSetAttribute(proj_pool_kernel, cudaFuncAttributeMaxDynamicSharedMemorySize, smem1);
    cudaFuncSetAttribute(attn_kernel,      cudaFuncAttributeMaxDynamicSharedMemorySize, smem2);

    proj_pool_kernel<<<dim3(32, 16), 256, smem1>>>(x, wq, wk, wv);
    attn_kernel<<<dim3(32, 16), 256, smem2>>>(x, wo, gamma, out);
}

// round 17
// speedup vs baseline: 1.0388x; 1.0388x over previous
#include <cuda_runtime.h>
#include <cuda_bf16.h>
#include <cstdint>

#define N_PIX 4096
#define M_PIX 1024

// cp.async helpers (16B per op)
#define CPA(dst32, srcp) \
    asm volatile("cp.async.ca.shared.global [%0], [%1], 16;" :: "r"(dst32), "l"(srcp) : "memory")
#define CP_COMMIT() asm volatile("cp.async.commit_group;" ::: "memory")
#define CP_WAIT0()  asm volatile("cp.async.wait_group 0;" ::: "memory")

// ldmatrix x4 (b16)
#define LDMX4(r0, r1, r2, r3, addr) \
    asm volatile("ldmatrix.sync.aligned.m8n8.x4.shared.b16 {%0,%1,%2,%3}, [%4];" \
        : "=r"(r0), "=r"(r1), "=r"(r2), "=r"(r3) : "r"(addr))
#define LDMX4T(r0, r1, r2, r3, addr) \
    asm volatile("ldmatrix.sync.aligned.m8n8.x4.trans.shared.b16 {%0,%1,%2,%3}, [%4];" \
        : "=r"(r0), "=r"(r1), "=r"(r2), "=r"(r3) : "r"(addr))

// m16n8k16 bf16 MMA, fp32 accumulate
#define MMA_BF16(d, a0, a1, a2, a3, b0, b1) \
    asm volatile("mma.sync.aligned.m16n8k16.row.col.f32.bf16.bf16.f32 " \
        "{%0,%1,%2,%3}, {%4,%5,%6,%7}, {%8,%9}, {%0,%1,%2,%3};" \
        : "+f"(d[0]), "+f"(d[1]), "+f"(d[2]), "+f"(d[3]) \
        : "r"(a0), "r"(a1), "r"(a2), "r"(a3), "r"(b0), "r"(b1))

__device__ __forceinline__ uint32_t pkbf(float a, float b) {
    __nv_bfloat162 h = __float22bfloat162_rn(make_float2(a, b));
    return *reinterpret_cast<uint32_t*>(&h);
}
__device__ __forceinline__ float ex2f(float x) {
    float r;
    asm("ex2.approx.f32 %0, %1;" : "=f"(r) : "f"(x));
    return r;
}

// Scratch (device globals — no allocation allowed)
__device__ __align__(16) __nv_bfloat16 g_q[16 * 16 * N_PIX];   // [b][16][n] bf16, pre-scaled log2(e)
__device__ __align__(16) __nv_bfloat16 g_k[16 * M_PIX * 16];   // [b][m][16] bf16
__device__ __align__(16) __nv_bfloat16 g_v[16 * 64 * M_PIX];   // [b][64][m] bf16

// ---------------------------------------------------------------------------
// Kernel 1 (R15 version, best measured ~18.5us): bf16 MMA + ldmatrix GEMM,
// x loaded LDG->CVT->STS bf16 directly, double-buffered; LDG of chunk kc+1
// issued before the sync so MMA(kc) hides its latency. 2x2 maxpool epilogue.
// ---------------------------------------------------------------------------
#define K1_W    0        // bf16 96x136 = 6528 fl
#define K1_XB0  6528     // bf16 32x136 = 2176 fl
#define K1_XB1  8704     // bf16 32x136 = 2176 fl
#define K1_SMEM 10880    // floats = 43520 B

__global__ __launch_bounds__(256, 2) void proj_pool_kernel(
    const float* __restrict__ x,
    const float* __restrict__ wq,
    const float* __restrict__ wk,
    const float* __restrict__ wv)
{
    extern __shared__ float sm[];
    __nv_bfloat16* sWb = (__nv_bfloat16*)(sm + K1_W);     // [96][136]

    const int t    = threadIdx.x;
    const int lane = t & 31;
    const int w    = t >> 5;
    const int g    = lane >> 2;
    const int tig  = lane & 3;
    const int b    = blockIdx.y;
    const int px0  = blockIdx.x * 128;

    const float* xb = x + (size_t)b * 128 * N_PIX;
    const uint32_t sbase = (uint32_t)__cvta_generic_to_shared(sm);

    const int xr_row = t >> 3;
    const int xr_col = (t & 7) * 4;

    float4 xr[4];
#pragma unroll
    for (int q = 0; q < 4; q++)
        xr[q] = *(const float4*)&xb[(size_t)xr_row * N_PIX + px0 + xr_col + q * 32];

    for (int i = t; i < 6144; i += 256) {
        int o = i >> 6, c2 = i & 63;
        const float* src = (o < 16) ? (wq + o * 128)
                         : (o < 32) ? (wk + (o - 16) * 128)
                                    : (wv + (o - 32) * 128);
        *(uint32_t*)(sWb + o * 136 + 2 * c2) = pkbf(src[2 * c2], src[2 * c2 + 1]);
    }

    float dd[6][8];
#pragma unroll
    for (int mt = 0; mt < 6; mt++)
#pragma unroll
        for (int j = 0; j < 8; j++) dd[mt][j] = 0.f;

    const int nA   = w * 16;
    const int matI = lane >> 3, ii = lane & 7;
    const uint32_t aOff = (uint32_t)(ii + 8 * (matI & 1)) * 272u + (uint32_t)(matI >> 1) * 16u;
    const uint32_t bOff = (uint32_t)(ii + 8 * (matI & 1)) * 272u + (uint32_t)(nA + 8 * (matI >> 1)) * 2u;

#pragma unroll 1
    for (int kc = 0; kc < 4; kc++) {
        const int buf = kc & 1;
        {
            __nv_bfloat16* xbuf = (__nv_bfloat16*)(sm + (buf ? K1_XB1 : K1_XB0));
#pragma unroll
            for (int q = 0; q < 4; q++) {
                uint2 u;
                u.x = pkbf(xr[q].x, xr[q].y);
                u.y = pkbf(xr[q].z, xr[q].w);
                *(uint2*)(xbuf + xr_row * 136 + xr_col + q * 32) = u;
            }
        }
        if (kc < 3) {
#pragma unroll
            for (int q = 0; q < 4; q++)
                xr[q] = *(const float4*)&xb[(size_t)(kc * 32 + 32 + xr_row) * N_PIX
                                            + px0 + xr_col + q * 32];
        }
        __syncthreads();

        const uint32_t aB = sbase + aOff;
        const uint32_t bB = sbase + (uint32_t)(buf ? K1_XB1 : K1_XB0) * 4u + bOff;
#pragma unroll
        for (int ks = 0; ks < 2; ks++) {
            uint32_t x0, x1, x2, x3;
            LDMX4T(x0, x1, x2, x3, bB + (uint32_t)ks * 16u * 272u);
#pragma unroll
            for (int mt = 0; mt < 6; mt++) {
                uint32_t a0, a1, a2, a3;
                LDMX4(a0, a1, a2, a3, aB + (uint32_t)(mt * 16) * 272u
                                         + (uint32_t)(kc * 64 + ks * 32));
                MMA_BF16((&dd[mt][0]), a0, a1, a2, a3, x0, x1);
                MMA_BF16((&dd[mt][4]), a0, a1, a2, a3, x2, x3);
            }
        }
    }
    __syncthreads();

    // ---- q: bf16, pre-scaled by log2(e) ----
    const float L2E = 1.44269504f;
#pragma unroll
    for (int nb = 0; nb < 2; nb++) {
        int n = nA + nb * 8 + 2 * tig;
        size_t qi0 = ((size_t)(b * 16 + g))     * N_PIX + px0 + n;
        size_t qi1 = ((size_t)(b * 16 + g + 8)) * N_PIX + px0 + n;
        *(uint32_t*)&g_q[qi0] = pkbf(dd[0][nb * 4]     * L2E, dd[0][nb * 4 + 1] * L2E);
        *(uint32_t*)&g_q[qi1] = pkbf(dd[0][nb * 4 + 2] * L2E, dd[0][nb * 4 + 3] * L2E);
    }

    // ---- k/v: horizontal max intra-thread -> pool scratch (aliases W) ----
    float* pb = sm;
#pragma unroll
    for (int mt = 1; mt < 6; mt++) {
#pragma unroll
        for (int nb = 0; nb < 2; nb++) {
            int n = nA + nb * 8 + 2 * tig;
            int rrow = n >> 6;
            int wp = (n & 63) >> 1;
            int ch = mt * 16 - 16 + g;
            pb[ch * 68 + rrow * 34 + wp]       = fmaxf(dd[mt][nb * 4],     dd[mt][nb * 4 + 1]);
            pb[(ch + 8) * 68 + rrow * 34 + wp] = fmaxf(dd[mt][nb * 4 + 2], dd[mt][nb * 4 + 3]);
        }
    }
    __syncthreads();

    const int mbase = blockIdx.x * 32;
    for (int i = t; i < 2560; i += 256) {
        int ch = i >> 5, wp = i & 31;
        float r = fmaxf(pb[ch * 68 + wp], pb[ch * 68 + 34 + wp]);
        if (ch < 16)
            g_k[((size_t)(b * M_PIX + mbase + wp)) * 16 + ch] = __float2bfloat16_rn(r);
        else
            g_v[((b * 64 + ch - 16) << 10) + mbase + wp] = __float2bfloat16_rn(r);
    }
}

// ---------------------------------------------------------------------------
// Kernel 2: FA2-style fused attention; rowsum ones-MMA split across two
// alternating accumulators (halves the serial D-dependency chain). Otherwise
// identical to R15/R16 attn.
// ---------------------------------------------------------------------------
#define SV_OFF(buf)  ((buf) ? 4352u : 0u)
#define SK_OFF(buf)  (8704u + ((buf) ? 1536u : 0u))
#define SO_OFF       0u      // bf16 [128][72] = 4608 fl
#define SWO_OFF      4608u   // bf16 [128][72] = 4608 fl
#define SSUM_OFF     17408u
#define SINV_OFF     17536u
#define SMEM2_FLOATS 17664

__device__ __forceinline__ void stage_chunk(
    uint32_t sbase, int buf, int chk, int t,
    const __nv_bfloat16* __restrict__ gkb, const __nv_bfloat16* __restrict__ gvb)
{
    uint32_t kdst = sbase + SK_OFF(buf) * 4u;
    uint32_t vdst = sbase + SV_OFF(buf) * 4u;
    {
        int m = t >> 1, h = t & 1;
        CPA(kdst + (uint32_t)m * 48u + (uint32_t)h * 16u,
            gkb + ((size_t)(chk * 128 + m)) * 16 + h * 8);
    }
#pragma unroll
    for (int q = 0; q < 4; q++) {
        int i = t + q * 256;
        int r = i >> 4, u = i & 15;
        CPA(vdst + (uint32_t)r * 272u + (uint32_t)u * 16u,
            gvb + ((size_t)r << 10) + chk * 128 + u * 8);
    }
}

__global__ __launch_bounds__(256, 2) void attn_kernel(
    const float* __restrict__ x,
    const float* __restrict__ wo,
    const float* __restrict__ gamma,
    float* __restrict__ out)
{
    extern __shared__ float sm[];
    float* sSum = sm + SSUM_OFF;
    float* sInv = sm + SINV_OFF;

    const int t    = threadIdx.x;
    const int w    = t >> 5;
    const int lane = t & 31;
    const int b    = blockIdx.y;
    const int n0   = blockIdx.x * 128;

    const int g    = lane >> 2;
    const int tig  = lane & 3;
    const int nw   = w * 16;
    const int matI = lane >> 3, ii = lane & 7;

    const uint32_t sbase = (uint32_t)__cvta_generic_to_shared(sm);
    const __nv_bfloat16* gkb = g_k + (size_t)b * M_PIX * 16;
    const __nv_bfloat16* gvb = g_v + (size_t)b * 64 * M_PIX;

    const uint32_t kOff = (uint32_t)(ii + 8 * (matI >> 1)) * 48u + (uint32_t)(matI & 1) * 16u;
    const uint32_t vOff = (uint32_t)(ii + 8 * (matI >> 1)) * 272u + (uint32_t)(matI & 1) * 16u;

    stage_chunk(sbase, 0, 0, t, gkb, gvb);
    CP_COMMIT();

    uint32_t qa0, qa1, qa2, qa3;
    {
        const __nv_bfloat16* gq = g_q + (size_t)b * 16 * N_PIX + n0;
        const int nq = nw + g;
#define QLD(d, n) ((uint32_t)*(const unsigned short*)&gq[(size_t)(d) * N_PIX + (n)])
        qa0 = QLD(2 * tig, nq)         | (QLD(2 * tig + 1, nq)     << 16);
        qa1 = QLD(2 * tig, nq + 8)     | (QLD(2 * tig + 1, nq + 8) << 16);
        qa2 = QLD(2 * tig + 8, nq)     | (QLD(2 * tig + 9, nq)     << 16);
        qa3 = QLD(2 * tig + 8, nq + 8) | (QLD(2 * tig + 9, nq + 8) << 16);
#undef QLD
    }

    float oc[8][4];
#pragma unroll
    for (int i = 0; i < 8; i++)
#pragma unroll
        for (int j = 0; j < 4; j++) oc[i][j] = 0.f;
    float rsd0[4] = {0.f, 0.f, 0.f, 0.f};   // rowsum acc (even j)
    float rsd1[4] = {0.f, 0.f, 0.f, 0.f};   // rowsum acc (odd j)
    const uint32_t ONE2 = 0x3F803F80u;

#pragma unroll 1
    for (int chk = 0; chk < 8; chk++) {
        const int buf = chk & 1;

        CP_WAIT0();
        __syncthreads();

        if (chk < 7) {
            stage_chunk(sbase, buf ^ 1, chk + 1, t, gkb, gvb);
            CP_COMMIT();
        }

        const uint32_t kBase = sbase + SK_OFF(buf) * 4u + kOff;
        const uint32_t vBase = sbase + SV_OFF(buf) * 4u + vOff;

#pragma unroll
        for (int h = 0; h < 2; h++) {
            float sd[8][4];
#pragma unroll
            for (int j = 0; j < 8; j++)
#pragma unroll
                for (int k = 0; k < 4; k++) sd[j][k] = 0.f;

#pragma unroll
            for (int u = 0; u < 4; u++) {
                uint32_t k0, k1, k2, k3;
                LDMX4(k0, k1, k2, k3, kBase + (uint32_t)(4 * h + u) * 768u);
                MMA_BF16(sd[2 * u],     qa0, qa1, qa2, qa3, k0, k1);
                MMA_BF16(sd[2 * u + 1], qa0, qa1, qa2, qa3, k2, k3);
            }

            uint32_t pa[4][4];
#pragma unroll
            for (int j = 0; j < 4; j++) {
                pa[j][0] = pkbf(ex2f(sd[2 * j][0]),     ex2f(sd[2 * j][1]));
                pa[j][1] = pkbf(ex2f(sd[2 * j][2]),     ex2f(sd[2 * j][3]));
                pa[j][2] = pkbf(ex2f(sd[2 * j + 1][0]), ex2f(sd[2 * j + 1][1]));
                pa[j][3] = pkbf(ex2f(sd[2 * j + 1][2]), ex2f(sd[2 * j + 1][3]));
                if (j & 1) { MMA_BF16(rsd1, pa[j][0], pa[j][1], pa[j][2], pa[j][3], ONE2, ONE2); }
                else       { MMA_BF16(rsd0, pa[j][0], pa[j][1], pa[j][2], pa[j][3], ONE2, ONE2); }
            }

#pragma unroll
            for (int kt = 0; kt < 4; kt++) {
                const uint32_t colb = (uint32_t)(4 * h + kt) * 32u;
#pragma unroll
                for (int cp = 0; cp < 4; cp++) {
                    uint32_t v0, v1, v2, v3;
                    LDMX4(v0, v1, v2, v3, vBase + (uint32_t)cp * 4352u + colb);
                    MMA_BF16(oc[2 * cp],     pa[kt][0], pa[kt][1], pa[kt][2], pa[kt][3], v0, v1);
                    MMA_BF16(oc[2 * cp + 1], pa[kt][0], pa[kt][1], pa[kt][2], pa[kt][3], v2, v3);
                }
            }
        }
    }
    __syncthreads();

    __nv_bfloat16* sO = (__nv_bfloat16*)(sm + SO_OFF);
#pragma unroll
    for (int ct = 0; ct < 8; ct++) {
        int c = 8 * ct + 2 * tig;
        *(uint32_t*)&sO[(nw + g) * 72 + c]     = pkbf(oc[ct][0], oc[ct][1]);
        *(uint32_t*)&sO[(nw + g + 8) * 72 + c] = pkbf(oc[ct][2], oc[ct][3]);
    }
    if (tig == 0) {
        sSum[nw + g]     = rsd0[0] + rsd1[0];
        sSum[nw + g + 8] = rsd0[2] + rsd1[2];
    }
    __nv_bfloat16* sWo = (__nv_bfloat16*)(sm + SWO_OFF);
    for (int i = t; i < 4096; i += 256) {
        int o = i >> 5, c2 = i & 31;
        *(uint32_t*)&sWo[o * 72 + 2 * c2] = pkbf(wo[o * 64 + 2 * c2], wo[o * 64 + 2 * c2 + 1]);
    }
    __syncthreads();

    if (t < 128) sInv[t] = 1.f / sSum[t];
    __syncthreads();

    {
        const int o0 = w * 16;
        const uint32_t aE = sbase + SWO_OFF * 4u
            + (uint32_t)(o0 + ii + 8 * (matI & 1)) * 144u + (uint32_t)(matI >> 1) * 16u;
        const uint32_t bE = sbase + SO_OFF * 4u
            + (uint32_t)(ii + 8 * (matI >> 1)) * 144u + (uint32_t)(matI & 1) * 16u;

        float od[16][4];
#pragma unroll
        for (int j = 0; j < 16; j++)
#pragma unroll
            for (int k = 0; k < 4; k++) od[j][k] = 0.f;

#pragma unroll
        for (int ks = 0; ks < 4; ks++) {
            uint32_t a0, a1, a2, a3;
            LDMX4(a0, a1, a2, a3, aE + (uint32_t)ks * 32u);
#pragma unroll
            for (int nt2 = 0; nt2 < 8; nt2++) {
                uint32_t b0, b1, b2, b3;
                LDMX4(b0, b1, b2, b3, bE + (uint32_t)nt2 * 16u * 144u + (uint32_t)ks * 32u);
                MMA_BF16(od[2 * nt2],     a0, a1, a2, a3, b0, b1);
                MMA_BF16(od[2 * nt2 + 1], a0, a1, a2, a3, b2, b3);
            }
        }

        const float gm = gamma[0];
#pragma unroll
        for (int nt = 0; nt < 16; nt++) {
            int nn = 8 * nt + 2 * tig;
            float s0 = gm * sInv[nn];
            float s1 = gm * sInv[nn + 1];
            size_t gi0 = ((size_t)(b * 128 + o0 + g)) * N_PIX + n0 + nn;
            size_t gi1 = ((size_t)(b * 128 + o0 + g + 8)) * N_PIX + n0 + nn;
            float2 x0 = *(const float2*)&x[gi0];
            float2 x1 = *(const float2*)&x[gi1];
            float2 r0, r1;
            r0.x = fmaf(s0, od[nt][0], x0.x);
            r0.y = fmaf(s1, od[nt][1], x0.y);
            r1.x = fmaf(s0, od[nt][2], x1.x);
            r1.y = fmaf(s1, od[nt][3], x1.y);
            *(float2*)&out[gi0] = r0;
            *(float2*)&out[gi1] = r1;
        }
    }
}

// ---------------------------------------------------------------------------
extern "C" void kernel_launch(void* const* d_in, const int* in_sizes, int n_in,
                              void* d_out, int out_size)
{
    const float* x     = (const float*)d_in[0];
    const float* wq    = (const float*)d_in[1];
    const float* wk    = (const float*)d_in[2];
    const float* wv    = (const float*)d_in[3];
    const float* wo    = (const float*)d_in[4];
    const float* gamma = (const float*)d_in[5];
    float* out = (float*)d_out;

    const int smem1 = K1_SMEM * 4;        // 43520
    const int smem2 = SMEM2_FLOATS * 4;   // 70656

    cudaFuncSetAttribute(proj_pool_kernel, cudaFuncAttributeMaxDynamicSharedMemorySize, smem1);
    cudaFuncSetAttribute(attn_kernel,      cudaFuncAttributeMaxDynamicSharedMemorySize, smem2);

    proj_pool_kernel<<<dim3(32, 16), 256, smem1>>>(x, wq, wk, wv);
    attn_kernel<<<dim3(32, 16), 256, smem2>>>(x, wo, gamma, out);
}